// round 12
// baseline (speedup 1.0000x reference)
#include <cuda_runtime.h>
#include <cuda_fp16.h>

// FastQuantumLLMOptimized: per-position cross-head attention.
// x: [16384, 32, 128] f32, patterns: [32,128] f32.
//   xh = x_pos * patterns ; s = xh xh^T / sqrt(128); a = softmax(s); out = a xh
//
// TWO WARPS per position, ONE position per CTA (18.1KB smem -> ~9-12 CTAs/SM,
// ~18+ warps vs 11.3 before). Per-position work and smem traffic identical to
// the 201us kernel; each phase is split across the two warps:
//   phase 2: warp w computes score rows 16w..16w+15 (4h x 8g tiles, 2-way
//            k-split reduced by one shfl_xor(16))
//   phase 4: warp w computes output granule half w (identical to the old
//            two-pass body with p := w, full 4-row b-reuse preserved)
// fp32 math with packed fma.rn.f32x2; attention weights fp16 in smem.
//
// Swizzle: xh float4 granules at h*32 + (c ^ ((h>>2)&7)); all main-loop LDS
// phase groups conflict-free. attn transposed [g][h] fp16, 64B per row.

#define NHEADS 32
#define HD 128

__device__ __forceinline__ unsigned long long pack2(float lo, float hi) {
    unsigned long long r;
    asm("mov.b64 %0, {%1, %2};" : "=l"(r) : "f"(lo), "f"(hi));
    return r;
}
__device__ __forceinline__ float2 unpack2(unsigned long long v) {
    float2 r;
    asm("mov.b64 {%0, %1}, %2;" : "=f"(r.x), "=f"(r.y) : "l"(v));
    return r;
}
__device__ __forceinline__ void fma2(unsigned long long &acc,
                                     unsigned long long a,
                                     unsigned long long b) {
    asm("fma.rn.f32x2 %0, %1, %2, %0;" : "+l"(acc) : "l"(a), "l"(b));
}

__global__ __launch_bounds__(64, 9)
void fq_attn_kernel(const float* __restrict__ x,
                    const float* __restrict__ patterns,
                    float* __restrict__ out)
{
    __shared__ __align__(16) float4 s_xh4[NHEADS * 32];       // 16 KB
    __shared__ __align__(16) __half s_at [NHEADS * 32 + 16];  // ~2 KB

    const int tid  = threadIdx.x;
    const int lane = tid & 31;
    const int w    = tid >> 5;
    const long long pos = blockIdx.x;

    // ---------------- Phase 1: load + modulate -> swizzled smem ------------
    {
        const float4* x4 = reinterpret_cast<const float4*>(x + pos * (NHEADS * HD));
        const float4* p4 = reinterpret_cast<const float4*>(patterns);
        #pragma unroll
        for (int i = 0; i < 16; i++) {
            int idx = tid + i * 64;           // float4 index 0..1023
            float4 xv = x4[idx];
            float4 pv = __ldg(&p4[idx]);
            int h = idx >> 5;
            int c = idx & 31;
            float4 r;
            r.x = xv.x * pv.x; r.y = xv.y * pv.y;
            r.z = xv.z * pv.z; r.w = xv.w * pv.w;
            s_xh4[h * 32 + (c ^ ((h >> 2) & 7))] = r;
        }
    }
    __syncthreads();

    // ---------------- Phase 2: warp w -> score rows 16w..16w+15 ------------
    // lane = kt(2, bit4) x ht(4, bits2-3) x gt(4, bits0-1).
    // Thread tile: 4h x 8g, k-half kt (c = kt*16 + s).
    {
        const int kt = lane >> 4;
        const int ht = (lane >> 2) & 3;
        const int gt = lane & 3;
        const int h0 = 16 * w + 4 * ht;
        const int g0 = 8 * gt;
        const int sa  = (4 * w + ht) & 7;     // swizzle of rows h0..h0+3
        const int sb0 = 2 * gt;               // swizzle of rows g0..g0+3
        const int sb1 = 2 * gt + 1;           // swizzle of rows g0+4..g0+7

        unsigned long long acc[4][8];
        #pragma unroll
        for (int i = 0; i < 4; i++)
            #pragma unroll
            for (int j = 0; j < 8; j++) acc[i][j] = 0ULL;

        #pragma unroll 4
        for (int s = 0; s < 16; s++) {
            const int c = kt * 16 + s;
            ulonglong2 a[4];
            #pragma unroll
            for (int i = 0; i < 4; i++)
                a[i] = *reinterpret_cast<const ulonglong2*>(&s_xh4[(h0 + i) * 32 + (c ^ sa)]);
            #pragma unroll
            for (int j = 0; j < 8; j++) {
                const int sb = (j < 4) ? sb0 : sb1;
                ulonglong2 b = *reinterpret_cast<const ulonglong2*>(&s_xh4[(g0 + j) * 32 + (c ^ sb)]);
                #pragma unroll
                for (int i = 0; i < 4; i++) {
                    fma2(acc[i][j], a[i].x, b.x);
                    fma2(acc[i][j], a[i].y, b.y);
                }
            }
        }

        // collapse f32x2, reduce k-halves (partner = lane^16), scale
        float v[4][8];
        #pragma unroll
        for (int i = 0; i < 4; i++)
            #pragma unroll
            for (int j = 0; j < 8; j++) {
                float2 u = unpack2(acc[i][j]);
                float p = u.x + u.y;
                p += __shfl_xor_sync(0xffffffffu, p, 16);
                v[i][j] = p * 0.08838834764831845f;   // 1/sqrt(128)
            }

        // softmax: 8 cols in-thread + gt (lane bits 0,1) via shfl
        float inv[4];
        #pragma unroll
        for (int i = 0; i < 4; i++) {
            float m = v[i][0];
            #pragma unroll
            for (int j = 1; j < 8; j++) m = fmaxf(m, v[i][j]);
            m = fmaxf(m, __shfl_xor_sync(0xffffffffu, m, 1));
            m = fmaxf(m, __shfl_xor_sync(0xffffffffu, m, 2));
            float s = 0.0f;
            #pragma unroll
            for (int j = 0; j < 8; j++) { v[i][j] = __expf(v[i][j] - m); s += v[i][j]; }
            s += __shfl_xor_sync(0xffffffffu, s, 1);
            s += __shfl_xor_sync(0xffffffffu, s, 2);
            inv[i] = 1.0f / s;
        }

        // store attn transposed fp16 (at[g*32 + h]); kt halves are duplicates,
        // so kt=0 stores rows {h0,h0+1}, kt=1 stores rows {h0+2,h0+3}.
        const int i0 = 2 * kt;
        #pragma unroll
        for (int j = 0; j < 8; j++) {
            __half2 q = __floats2half2_rn(v[i0][j] * inv[i0], v[i0 + 1][j] * inv[i0 + 1]);
            *reinterpret_cast<__half2*>(&s_at[(g0 + j) * 32 + h0 + i0]) = q;
        }
    }
    __syncthreads();

    // ---------------- Phase 4: warp w -> output granule half w -------------
    // lane = hq(8) x dt(4); thread tile 4h x 16d (ch = 16w + 4t + dt).
    {
        const int dt = lane & 3;
        const int hq = lane >> 2;
        const int H0 = hq * 4;
        float* outp = out + pos * (NHEADS * HD);

        unsigned long long acc[4][4][2];
        #pragma unroll
        for (int i = 0; i < 4; i++)
            #pragma unroll
            for (int t = 0; t < 4; t++) { acc[i][t][0] = 0ULL; acc[i][t][1] = 0ULL; }

        #pragma unroll 4
        for (int g = 0; g < 32; g++) {
            uint2 qa = *reinterpret_cast<const uint2*>(&s_at[g * 32 + H0]);
            float2 f01 = __half22float2(*reinterpret_cast<__half2*>(&qa.x));
            float2 f23 = __half22float2(*reinterpret_cast<__half2*>(&qa.y));
            unsigned long long a2[4];
            a2[0] = pack2(f01.x, f01.x);
            a2[1] = pack2(f01.y, f01.y);
            a2[2] = pack2(f23.x, f23.x);
            a2[3] = pack2(f23.y, f23.y);
            const int sg = (g >> 2) & 7;
            #pragma unroll
            for (int t = 0; t < 4; t++) {
                const int ch = 16 * w + t * 4 + dt;
                ulonglong2 bb = *reinterpret_cast<const ulonglong2*>(&s_xh4[g * 32 + (ch ^ sg)]);
                #pragma unroll
                for (int i = 0; i < 4; i++) {
                    fma2(acc[i][t][0], a2[i], bb.x);
                    fma2(acc[i][t][1], a2[i], bb.y);
                }
            }
        }

        #pragma unroll
        for (int i = 0; i < 4; i++)
            #pragma unroll
            for (int t = 0; t < 4; t++) {
                const int ch = 16 * w + t * 4 + dt;
                float2 u0 = unpack2(acc[i][t][0]);
                float2 u1 = unpack2(acc[i][t][1]);
                *reinterpret_cast<float4*>(&outp[(H0 + i) * HD + ch * 4])
                    = make_float4(u0.x, u0.y, u1.x, u1.y);
            }
    }
}

extern "C" void kernel_launch(void* const* d_in, const int* in_sizes, int n_in,
                              void* d_out, int out_size) {
    const float* x        = (const float*)d_in[0];
    const float* patterns = (const float*)d_in[1];
    float* out            = (float*)d_out;
    const int positions   = in_sizes[0] / (NHEADS * HD);   // 16384
    fq_attn_kernel<<<positions, 64>>>(x, patterns, out);
}

// round 13
// speedup vs baseline: 1.9726x; 1.9726x over previous
#include <cuda_runtime.h>
#include <cuda_fp16.h>

// FastQuantumLLMOptimized: per-position cross-head attention, tensor-core path.
// x: [16384, 32, 128] f32, patterns: [32,128] f32.
//   xh = x_pos * patterns ; s = xh xh^T / sqrt(128); a = softmax(s); out = a xh
//
// ONE WARP per position (CTA = 2 warps = 2 positions, 32KB smem).
// GEMMs via mma.sync.m16n8k16 (HMMA) with fp16 error-free hi/lo split:
//   xh = hi + lo (fp16 each);  scores = hi*hi + hi*lo + lo*hi  (~fp32-exact)
//   out = attn_fp16 * (hi + lo)
// Softmax runs on fp32 C-fragments in registers (2 shfl rounds); attn C-frags
// repack directly into GEMM2 A-frags (layouts coincide) — no smem round-trip.
//
// smem: xh_hi/xh_lo as fp16, 256B rows, 16B-granule XOR swizzle g^(h&7):
// every ldmatrix 8-lane address group covers 8 distinct bank-groups.

#define NHEADS 32
#define HD 128
#define SCALE 0.08838834764831845f   // 1/sqrt(128)

__device__ __forceinline__ unsigned smem_u32(const void* p) {
    unsigned r;
    asm("{ .reg .u64 t; cvta.to.shared.u64 t, %1; cvt.u32.u64 %0, t; }"
        : "=r"(r) : "l"(p));
    return r;
}
__device__ __forceinline__ void ldsm4(unsigned a, unsigned* r) {
    asm volatile("ldmatrix.sync.aligned.m8n8.x4.shared.b16 {%0,%1,%2,%3}, [%4];"
                 : "=r"(r[0]), "=r"(r[1]), "=r"(r[2]), "=r"(r[3]) : "r"(a));
}
__device__ __forceinline__ void ldsm4t(unsigned a, unsigned* r) {
    asm volatile("ldmatrix.sync.aligned.m8n8.x4.trans.shared.b16 {%0,%1,%2,%3}, [%4];"
                 : "=r"(r[0]), "=r"(r[1]), "=r"(r[2]), "=r"(r[3]) : "r"(a));
}
__device__ __forceinline__ void mma16816(float* c, const unsigned* a, const unsigned* b) {
    asm volatile("mma.sync.aligned.m16n8k16.row.col.f32.f16.f16.f32 "
                 "{%0,%1,%2,%3}, {%4,%5,%6,%7}, {%8,%9}, {%0,%1,%2,%3};"
                 : "+f"(c[0]), "+f"(c[1]), "+f"(c[2]), "+f"(c[3])
                 : "r"(a[0]), "r"(a[1]), "r"(a[2]), "r"(a[3]),
                   "r"(b[0]), "r"(b[1]));
}
// pack {lo, hi} fp32 -> f16x2 register (lo in lower half)
__device__ __forceinline__ unsigned pk_h2(float lo, float hi) {
    unsigned r;
    asm("cvt.rn.f16x2.f32 %0, %1, %2;" : "=r"(r) : "f"(hi), "f"(lo));
    return r;
}

__global__ __launch_bounds__(64)
void fq_attn_kernel(const float* __restrict__ x,
                    const float* __restrict__ patterns,
                    float* __restrict__ out)
{
    __shared__ __align__(16) __half s_hi[2][NHEADS * HD];  // 2 x 8 KB
    __shared__ __align__(16) __half s_lo[2][NHEADS * HD];  // 2 x 8 KB

    const int lane = threadIdx.x & 31;
    const int w    = threadIdx.x >> 5;
    const long long pos = 2LL * blockIdx.x + w;

    __half* hb = s_hi[w];
    __half* lb = s_lo[w];
    const unsigned hiu = smem_u32(hb);
    const unsigned lou = smem_u32(lb);

    // ---------------- Phase 1: xh = x*patterns, split fp16 hi/lo -> smem ---
    // lane owns elements 4*lane..4*lane+3 of each row; 16B granule g=lane>>1,
    // physical granule g ^ (h&7), 8B sub-slot lane&1.
    {
        const float4* x4 = reinterpret_cast<const float4*>(x + pos * (NHEADS * HD));
        const float4* p4 = reinterpret_cast<const float4*>(patterns);
        const int g   = lane >> 1;
        const int sub = (lane & 1) * 4;
        #pragma unroll 8
        for (int h = 0; h < 32; h++) {
            float4 xv = x4[h * 32 + lane];
            float4 pv = __ldg(&p4[h * 32 + lane]);
            float rx = xv.x * pv.x, ry = xv.y * pv.y;
            float rz = xv.z * pv.z, rw = xv.w * pv.w;
            __half ax = __float2half_rn(rx), ay = __float2half_rn(ry);
            __half az = __float2half_rn(rz), aw = __float2half_rn(rw);
            float ex = rx - __half2float(ax), ey = ry - __half2float(ay);
            float ez = rz - __half2float(az), ew = rw - __half2float(aw);
            const int idx = h * 128 + ((g ^ (h & 7)) << 3) + sub;
            uint2 hv, lv;
            hv.x = pk_h2(__half2float(ax), __half2float(ay));
            hv.y = pk_h2(__half2float(az), __half2float(aw));
            lv.x = pk_h2(ex, ey);
            lv.y = pk_h2(ez, ew);
            *reinterpret_cast<uint2*>(&hb[idx]) = hv;
            *reinterpret_cast<uint2*>(&lb[idx]) = lv;
        }
    }
    __syncwarp();

    // ---------------- GEMM1: S = hi*hi + hi*lo + lo*hi  (32x32, k=128) -----
    float c1[2][4][4];
    #pragma unroll
    for (int mt = 0; mt < 2; mt++)
        #pragma unroll
        for (int nt = 0; nt < 4; nt++)
            #pragma unroll
            for (int z = 0; z < 4; z++) c1[mt][nt][z] = 0.0f;

    {
        const int rowA = (lane & 7) + ((lane >> 3) & 1) * 8;  // A group rows
        const int rowB = (lane & 7) + (lane >> 4) * 8;        // B group rows
        #pragma unroll 2
        for (int kt = 0; kt < 8; kt++) {
            const int granA = 2 * kt + (lane >> 4);
            const int granB = 2 * kt + ((lane >> 3) & 1);
            unsigned ah[2][4], al[2][4], bh[2][4], bl[2][4];
            #pragma unroll
            for (int mt = 0; mt < 2; mt++) {
                const int row = 16 * mt + rowA;
                const unsigned off = row * 256 + ((granA ^ (row & 7)) << 4);
                ldsm4(hiu + off, ah[mt]);
                ldsm4(lou + off, al[mt]);
            }
            #pragma unroll
            for (int p = 0; p < 2; p++) {
                const int row = 16 * p + rowB;
                const unsigned off = row * 256 + ((granB ^ (row & 7)) << 4);
                ldsm4(hiu + off, bh[p]);
                ldsm4(lou + off, bl[p]);
            }
            #pragma unroll
            for (int mt = 0; mt < 2; mt++)
                #pragma unroll
                for (int nt = 0; nt < 4; nt++) {
                    const unsigned* bfh = &bh[nt >> 1][(nt & 1) * 2];
                    const unsigned* bfl = &bl[nt >> 1][(nt & 1) * 2];
                    mma16816(c1[mt][nt], ah[mt], bfh);   // hi*hi
                    mma16816(c1[mt][nt], ah[mt], bfl);   // hi*lo
                    mma16816(c1[mt][nt], al[mt], bfh);   // lo*hi
                }
        }
    }

    // ---------------- Softmax on C fragments (rows on lane>>2 groups) ------
    // c1[mt][nt] = {(r,2q),(r,2q+1),(r+8,2q),(r+8,2q+1)} with r=lane>>2,
    // cols 8nt+2q(+1).  Row-half rh: regs {2rh, 2rh+1} across nt = 8 cols.
    #pragma unroll
    for (int mt = 0; mt < 2; mt++)
        #pragma unroll
        for (int rh = 0; rh < 2; rh++) {
            float v[8];
            #pragma unroll
            for (int nt = 0; nt < 4; nt++) {
                v[2 * nt]     = c1[mt][nt][2 * rh]     * SCALE;
                v[2 * nt + 1] = c1[mt][nt][2 * rh + 1] * SCALE;
            }
            float m = v[0];
            #pragma unroll
            for (int j = 1; j < 8; j++) m = fmaxf(m, v[j]);
            m = fmaxf(m, __shfl_xor_sync(0xffffffffu, m, 1));
            m = fmaxf(m, __shfl_xor_sync(0xffffffffu, m, 2));
            float s = 0.0f;
            #pragma unroll
            for (int j = 0; j < 8; j++) { v[j] = __expf(v[j] - m); s += v[j]; }
            s += __shfl_xor_sync(0xffffffffu, s, 1);
            s += __shfl_xor_sync(0xffffffffu, s, 2);
            const float inv = 1.0f / s;
            #pragma unroll
            for (int nt = 0; nt < 4; nt++) {
                c1[mt][nt][2 * rh]     = v[2 * nt]     * inv;
                c1[mt][nt][2 * rh + 1] = v[2 * nt + 1] * inv;
            }
        }

    // ---------------- Repack attn C-frags -> GEMM2 A-frags (fp16) ----------
    // A-frag(mt,kt2) regs: {(r,2q),(r,2q+1)} {(r+8,..)} {(r,2q+8)..} {(r+8,..)}
    // = n-frags 2kt2 (cols 0-7 of k-tile) and 2kt2+1 (cols 8-15).
    unsigned a2[2][2][4];
    #pragma unroll
    for (int mt = 0; mt < 2; mt++)
        #pragma unroll
        for (int kt2 = 0; kt2 < 2; kt2++) {
            a2[mt][kt2][0] = pk_h2(c1[mt][2 * kt2][0],     c1[mt][2 * kt2][1]);
            a2[mt][kt2][1] = pk_h2(c1[mt][2 * kt2][2],     c1[mt][2 * kt2][3]);
            a2[mt][kt2][2] = pk_h2(c1[mt][2 * kt2 + 1][0], c1[mt][2 * kt2 + 1][1]);
            a2[mt][kt2][3] = pk_h2(c1[mt][2 * kt2 + 1][2], c1[mt][2 * kt2 + 1][3]);
        }

    // ---------------- GEMM2: out = attn * (hi + lo)  (32x128, k=32) --------
    {
        float* outp = out + pos * (NHEADS * HD);
        const int q = lane & 3;
        const int r = lane >> 2;

        for (int nc = 0; nc < 4; nc++) {            // 32-col output chunks
            float c2[2][4][4];
            #pragma unroll
            for (int mt = 0; mt < 2; mt++)
                #pragma unroll
                for (int dt = 0; dt < 4; dt++)
                    #pragma unroll
                    for (int z = 0; z < 4; z++) c2[mt][dt][z] = 0.0f;

            #pragma unroll
            for (int kt2 = 0; kt2 < 2; kt2++) {
                const int rowG = 16 * kt2 + (lane & 7) + ((lane >> 3) & 1) * 8;
                unsigned b2h[2][4], b2l[2][4];
                #pragma unroll
                for (int p = 0; p < 2; p++) {
                    const int gran = 4 * nc + 2 * p + (lane >> 4);
                    const unsigned off = rowG * 256 + ((gran ^ (rowG & 7)) << 4);
                    ldsm4t(hiu + off, b2h[p]);
                    ldsm4t(lou + off, b2l[p]);
                }
                #pragma unroll
                for (int mt = 0; mt < 2; mt++)
                    #pragma unroll
                    for (int dt = 0; dt < 4; dt++) {
                        const unsigned* bfh = &b2h[dt >> 1][(dt & 1) * 2];
                        const unsigned* bfl = &b2l[dt >> 1][(dt & 1) * 2];
                        mma16816(c2[mt][dt], a2[mt][kt2], bfh);
                        mma16816(c2[mt][dt], a2[mt][kt2], bfl);
                    }
            }

            #pragma unroll
            for (int mt = 0; mt < 2; mt++)
                #pragma unroll
                for (int dt = 0; dt < 4; dt++) {
                    const int col  = 32 * nc + 8 * dt + 2 * q;
                    const int row0 = 16 * mt + r;
                    *reinterpret_cast<float2*>(&outp[row0 * HD + col])
                        = make_float2(c2[mt][dt][0], c2[mt][dt][1]);
                    *reinterpret_cast<float2*>(&outp[(row0 + 8) * HD + col])
                        = make_float2(c2[mt][dt][2], c2[mt][dt][3]);
                }
        }
    }
}

extern "C" void kernel_launch(void* const* d_in, const int* in_sizes, int n_in,
                              void* d_out, int out_size) {
    const float* x        = (const float*)d_in[0];
    const float* patterns = (const float*)d_in[1];
    float* out            = (float*)d_out;
    const int positions   = in_sizes[0] / (NHEADS * HD);   // 16384 (even)
    fq_attn_kernel<<<positions / 2, 64>>>(x, patterns, out);
}

// round 14
// speedup vs baseline: 2.2984x; 1.1652x over previous
#include <cuda_runtime.h>
#include <cuda_fp16.h>

// FastQuantumLLMOptimized: per-position cross-head attention, tensor-core path.
// x: [16384, 32, 128] f32, patterns: [32,128] f32.
//   xh = x_pos * patterns ; s = xh xh^T / sqrt(128); a = softmax(s); out = a xh
//
// TWO WARPS per position, ONE position per CTA (16.4KB smem -> 8 CTAs = 16
// warps/SM under __launch_bounds__(64,8)). Warp w owns score/output rows
// 16w..16w+15. GEMMs via mma.sync.m16n8k16 (HMMA), fp16 error-free hi/lo split:
//   GEMM1: scores = hi*hi + hi*lo + lo*hi  (~fp32-exact)
//   GEMM2: out    = attn_fp16 * hi          (xh fp16 error ~1.5e-4, gate 1e-3)
// Softmax on fp32 C-fragments in registers; attn C-frags repack in-register to
// GEMM2 A-frags (fragment layouts coincide) — attn never touches smem.
//
// smem: xh hi/lo fp16, 256B rows, 16B-granule XOR swizzle g^(h&7): every
// ldmatrix 8-lane address group covers 8 distinct bank-groups.

#define NHEADS 32
#define HD 128
#define SCALE 0.08838834764831845f   // 1/sqrt(128)

__device__ __forceinline__ unsigned smem_u32(const void* p) {
    unsigned r;
    asm("{ .reg .u64 t; cvta.to.shared.u64 t, %1; cvt.u32.u64 %0, t; }"
        : "=r"(r) : "l"(p));
    return r;
}
__device__ __forceinline__ void ldsm4(unsigned a, unsigned* r) {
    asm volatile("ldmatrix.sync.aligned.m8n8.x4.shared.b16 {%0,%1,%2,%3}, [%4];"
                 : "=r"(r[0]), "=r"(r[1]), "=r"(r[2]), "=r"(r[3]) : "r"(a));
}
__device__ __forceinline__ void ldsm4t(unsigned a, unsigned* r) {
    asm volatile("ldmatrix.sync.aligned.m8n8.x4.trans.shared.b16 {%0,%1,%2,%3}, [%4];"
                 : "=r"(r[0]), "=r"(r[1]), "=r"(r[2]), "=r"(r[3]) : "r"(a));
}
__device__ __forceinline__ void mma16816(float* c, const unsigned* a, const unsigned* b) {
    asm volatile("mma.sync.aligned.m16n8k16.row.col.f32.f16.f16.f32 "
                 "{%0,%1,%2,%3}, {%4,%5,%6,%7}, {%8,%9}, {%0,%1,%2,%3};"
                 : "+f"(c[0]), "+f"(c[1]), "+f"(c[2]), "+f"(c[3])
                 : "r"(a[0]), "r"(a[1]), "r"(a[2]), "r"(a[3]),
                   "r"(b[0]), "r"(b[1]));
}
// pack {lo, hi} fp32 -> f16x2 register (lo in lower half)
__device__ __forceinline__ unsigned pk_h2(float lo, float hi) {
    unsigned r;
    asm("cvt.rn.f16x2.f32 %0, %1, %2;" : "=r"(r) : "f"(hi), "f"(lo));
    return r;
}

__global__ __launch_bounds__(64, 8)
void fq_attn_kernel(const float* __restrict__ x,
                    const float* __restrict__ patterns,
                    float* __restrict__ out)
{
    __shared__ __align__(16) __half s_hi[NHEADS * HD];  // 8 KB
    __shared__ __align__(16) __half s_lo[NHEADS * HD];  // 8 KB

    const int lane = threadIdx.x & 31;
    const int w    = threadIdx.x >> 5;
    const long long pos = blockIdx.x;

    const unsigned hiu = smem_u32(s_hi);
    const unsigned lou = smem_u32(s_lo);

    // ---------------- Phase 1: xh = x*patterns, split fp16 hi/lo -> smem ---
    // warp w writes rows 16w..16w+15; lane owns 16B of each row.
    {
        const float4* x4 = reinterpret_cast<const float4*>(x + pos * (NHEADS * HD));
        const float4* p4 = reinterpret_cast<const float4*>(patterns);
        const int g   = lane >> 1;
        const int sub = (lane & 1) * 4;
        #pragma unroll 4
        for (int i = 0; i < 16; i++) {
            const int h = 16 * w + i;
            float4 xv = x4[h * 32 + lane];
            float4 pv = __ldg(&p4[h * 32 + lane]);
            float rx = xv.x * pv.x, ry = xv.y * pv.y;
            float rz = xv.z * pv.z, rw = xv.w * pv.w;
            __half ax = __float2half_rn(rx), ay = __float2half_rn(ry);
            __half az = __float2half_rn(rz), aw = __float2half_rn(rw);
            float ex = rx - __half2float(ax), ey = ry - __half2float(ay);
            float ez = rz - __half2float(az), ew = rw - __half2float(aw);
            const int idx = h * 128 + ((g ^ (h & 7)) << 3) + sub;
            uint2 hv, lv;
            hv.x = pk_h2(__half2float(ax), __half2float(ay));
            hv.y = pk_h2(__half2float(az), __half2float(aw));
            lv.x = pk_h2(ex, ey);
            lv.y = pk_h2(ez, ew);
            *reinterpret_cast<uint2*>(&s_hi[idx]) = hv;
            *reinterpret_cast<uint2*>(&s_lo[idx]) = lv;
        }
    }
    __syncthreads();

    // ---------------- GEMM1: S rows 16w.. = hi*hi + hi*lo + lo*hi ----------
    float c1[4][4];
    #pragma unroll
    for (int nt = 0; nt < 4; nt++)
        #pragma unroll
        for (int z = 0; z < 4; z++) c1[nt][z] = 0.0f;

    {
        const int rowA = 16 * w + (lane & 7) + ((lane >> 3) & 1) * 8;
        const int rowB = (lane & 7) + (lane >> 4) * 8;
        #pragma unroll 2
        for (int kt = 0; kt < 8; kt++) {
            const int granA = 2 * kt + (lane >> 4);
            const int granB = 2 * kt + ((lane >> 3) & 1);
            unsigned ah[4], al[4], bh[2][4], bl[2][4];
            {
                const unsigned off = rowA * 256 + ((granA ^ (rowA & 7)) << 4);
                ldsm4(hiu + off, ah);
                ldsm4(lou + off, al);
            }
            #pragma unroll
            for (int p = 0; p < 2; p++) {
                const int row = 16 * p + rowB;
                const unsigned off = row * 256 + ((granB ^ (row & 7)) << 4);
                ldsm4(hiu + off, bh[p]);
                ldsm4(lou + off, bl[p]);
            }
            #pragma unroll
            for (int nt = 0; nt < 4; nt++) {
                const unsigned* bfh = &bh[nt >> 1][(nt & 1) * 2];
                const unsigned* bfl = &bl[nt >> 1][(nt & 1) * 2];
                mma16816(c1[nt], ah, bfh);   // hi*hi
                mma16816(c1[nt], ah, bfl);   // hi*lo
                mma16816(c1[nt], al, bfh);   // lo*hi
            }
        }
    }

    // ---------------- Softmax on C fragments (rows on lane>>2 groups) ------
    // c1[nt] = {(r,2q),(r,2q+1),(r+8,2q),(r+8,2q+1)}; cols 8nt+2q(+1).
    #pragma unroll
    for (int rh = 0; rh < 2; rh++) {
        float v[8];
        #pragma unroll
        for (int nt = 0; nt < 4; nt++) {
            v[2 * nt]     = c1[nt][2 * rh]     * SCALE;
            v[2 * nt + 1] = c1[nt][2 * rh + 1] * SCALE;
        }
        float m = v[0];
        #pragma unroll
        for (int j = 1; j < 8; j++) m = fmaxf(m, v[j]);
        m = fmaxf(m, __shfl_xor_sync(0xffffffffu, m, 1));
        m = fmaxf(m, __shfl_xor_sync(0xffffffffu, m, 2));
        float s = 0.0f;
        #pragma unroll
        for (int j = 0; j < 8; j++) { v[j] = __expf(v[j] - m); s += v[j]; }
        s += __shfl_xor_sync(0xffffffffu, s, 1);
        s += __shfl_xor_sync(0xffffffffu, s, 2);
        const float inv = 1.0f / s;
        #pragma unroll
        for (int nt = 0; nt < 4; nt++) {
            c1[nt][2 * rh]     = v[2 * nt]     * inv;
            c1[nt][2 * rh + 1] = v[2 * nt + 1] * inv;
        }
    }

    // ---------------- Repack attn C-frags -> GEMM2 A-frags (fp16) ----------
    unsigned a2[2][4];
    #pragma unroll
    for (int kt2 = 0; kt2 < 2; kt2++) {
        a2[kt2][0] = pk_h2(c1[2 * kt2][0],     c1[2 * kt2][1]);
        a2[kt2][1] = pk_h2(c1[2 * kt2][2],     c1[2 * kt2][3]);
        a2[kt2][2] = pk_h2(c1[2 * kt2 + 1][0], c1[2 * kt2 + 1][1]);
        a2[kt2][3] = pk_h2(c1[2 * kt2 + 1][2], c1[2 * kt2 + 1][3]);
    }

    // ---------------- GEMM2: out rows 16w.. = attn * hi  (k=32) ------------
    {
        float* outp = out + pos * (NHEADS * HD);
        const int q = lane & 3;
        const int r = lane >> 2;

        #pragma unroll
        for (int nc = 0; nc < 4; nc++) {            // 32-col output chunks
            float c2[4][4];
            #pragma unroll
            for (int dt = 0; dt < 4; dt++)
                #pragma unroll
                for (int z = 0; z < 4; z++) c2[dt][z] = 0.0f;

            #pragma unroll
            for (int kt2 = 0; kt2 < 2; kt2++) {
                const int rowG = 16 * kt2 + (lane & 7) + ((lane >> 3) & 1) * 8;
                unsigned b2h[2][4];
                #pragma unroll
                for (int p = 0; p < 2; p++) {
                    const int gran = 4 * nc + 2 * p + (lane >> 4);
                    const unsigned off = rowG * 256 + ((gran ^ (rowG & 7)) << 4);
                    ldsm4t(hiu + off, b2h[p]);
                }
                #pragma unroll
                for (int dt = 0; dt < 4; dt++)
                    mma16816(c2[dt], a2[kt2], &b2h[dt >> 1][(dt & 1) * 2]);
            }

            #pragma unroll
            for (int dt = 0; dt < 4; dt++) {
                const int col  = 32 * nc + 8 * dt + 2 * q;
                const int row0 = 16 * w + r;
                *reinterpret_cast<float2*>(&outp[row0 * HD + col])
                    = make_float2(c2[dt][0], c2[dt][1]);
                *reinterpret_cast<float2*>(&outp[(row0 + 8) * HD + col])
                    = make_float2(c2[dt][2], c2[dt][3]);
            }
        }
    }
}

extern "C" void kernel_launch(void* const* d_in, const int* in_sizes, int n_in,
                              void* d_out, int out_size) {
    const float* x        = (const float*)d_in[0];
    const float* patterns = (const float*)d_in[1];
    float* out            = (float*)d_out;
    const int positions   = in_sizes[0] / (NHEADS * HD);   // 16384
    fq_attn_kernel<<<positions, 64>>>(x, patterns, out);
}

// round 15
// speedup vs baseline: 2.5462x; 1.1078x over previous
#include <cuda_runtime.h>
#include <cuda_fp16.h>

// FastQuantumLLMOptimized: per-position cross-head attention, tensor-core path.
// x: [16384, 32, 128] f32, patterns: [32,128] f32.
//   xh = x_pos * patterns ; s = xh xh^T / sqrt(128); a = softmax(s); out = a xh
//
// TWO WARPS per position, ONE position per CTA (16.4KB smem, 9 CTAs = 18
// warps/SM). Warp w owns score/output rows 16w..16w+15.
// GEMMs via mma.sync.m16n8k16 (HMMA), fp16 error-free hi/lo split of xh:
//   GEMM1: scores = (hi+lo)*hi = xh*hi^T   (residual xh*lo ~1e-4, dropped)
//   GEMM2: out    = attn_fp16 * hi
// Softmax on fp32 C-fragments in registers; attn C-frags repack in-register to
// GEMM2 A-frags (fragment layouts coincide) — attn never touches smem.
//
// smem: xh hi/lo fp16, 256B rows, 16B-granule XOR swizzle g^(h&7): every
// ldmatrix 8-lane address group covers 8 distinct bank-groups.

#define NHEADS 32
#define HD 128
#define SCALE 0.08838834764831845f   // 1/sqrt(128)

__device__ __forceinline__ unsigned smem_u32(const void* p) {
    unsigned r;
    asm("{ .reg .u64 t; cvta.to.shared.u64 t, %1; cvt.u32.u64 %0, t; }"
        : "=r"(r) : "l"(p));
    return r;
}
__device__ __forceinline__ void ldsm4(unsigned a, unsigned* r) {
    asm volatile("ldmatrix.sync.aligned.m8n8.x4.shared.b16 {%0,%1,%2,%3}, [%4];"
                 : "=r"(r[0]), "=r"(r[1]), "=r"(r[2]), "=r"(r[3]) : "r"(a));
}
__device__ __forceinline__ void ldsm4t(unsigned a, unsigned* r) {
    asm volatile("ldmatrix.sync.aligned.m8n8.x4.trans.shared.b16 {%0,%1,%2,%3}, [%4];"
                 : "=r"(r[0]), "=r"(r[1]), "=r"(r[2]), "=r"(r[3]) : "r"(a));
}
__device__ __forceinline__ void mma16816(float* c, const unsigned* a, const unsigned* b) {
    asm volatile("mma.sync.aligned.m16n8k16.row.col.f32.f16.f16.f32 "
                 "{%0,%1,%2,%3}, {%4,%5,%6,%7}, {%8,%9}, {%0,%1,%2,%3};"
                 : "+f"(c[0]), "+f"(c[1]), "+f"(c[2]), "+f"(c[3])
                 : "r"(a[0]), "r"(a[1]), "r"(a[2]), "r"(a[3]),
                   "r"(b[0]), "r"(b[1]));
}
// pack {lo, hi} fp32 -> f16x2 register (lo in lower half)
__device__ __forceinline__ unsigned pk_h2(float lo, float hi) {
    unsigned r;
    asm("cvt.rn.f16x2.f32 %0, %1, %2;" : "=r"(r) : "f"(hi), "f"(lo));
    return r;
}

__global__ __launch_bounds__(64, 9)
void fq_attn_kernel(const float* __restrict__ x,
                    const float* __restrict__ patterns,
                    float* __restrict__ out)
{
    __shared__ __align__(16) __half s_hi[NHEADS * HD];  // 8 KB
    __shared__ __align__(16) __half s_lo[NHEADS * HD];  // 8 KB

    const int lane = threadIdx.x & 31;
    const int w    = threadIdx.x >> 5;
    const long long pos = blockIdx.x;

    const unsigned hiu = smem_u32(s_hi);
    const unsigned lou = smem_u32(s_lo);

    // ---------------- Phase 1: xh = x*patterns, split fp16 hi/lo -> smem ---
    // warp w writes rows 16w..16w+15; lane owns 16B of each row.
    {
        const float4* x4 = reinterpret_cast<const float4*>(x + pos * (NHEADS * HD));
        const float4* p4 = reinterpret_cast<const float4*>(patterns);
        const int g   = lane >> 1;
        const int sub = (lane & 1) * 4;
        #pragma unroll 8
        for (int i = 0; i < 16; i++) {
            const int h = 16 * w + i;
            float4 xv = x4[h * 32 + lane];
            float4 pv = __ldg(&p4[h * 32 + lane]);
            float rx = xv.x * pv.x, ry = xv.y * pv.y;
            float rz = xv.z * pv.z, rw = xv.w * pv.w;
            __half ax = __float2half_rn(rx), ay = __float2half_rn(ry);
            __half az = __float2half_rn(rz), aw = __float2half_rn(rw);
            float ex = rx - __half2float(ax), ey = ry - __half2float(ay);
            float ez = rz - __half2float(az), ew = rw - __half2float(aw);
            const int idx = h * 128 + ((g ^ (h & 7)) << 3) + sub;
            uint2 hv, lv;
            hv.x = pk_h2(__half2float(ax), __half2float(ay));
            hv.y = pk_h2(__half2float(az), __half2float(aw));
            lv.x = pk_h2(ex, ey);
            lv.y = pk_h2(ez, ew);
            *reinterpret_cast<uint2*>(&s_hi[idx]) = hv;
            *reinterpret_cast<uint2*>(&s_lo[idx]) = lv;
        }
    }
    __syncthreads();

    // ---------------- GEMM1: S rows 16w.. = (hi+lo)*hi^T -------------------
    float c1[4][4];
    #pragma unroll
    for (int nt = 0; nt < 4; nt++)
        #pragma unroll
        for (int z = 0; z < 4; z++) c1[nt][z] = 0.0f;

    {
        const int rowA = 16 * w + (lane & 7) + ((lane >> 3) & 1) * 8;
        const int rowB = (lane & 7) + (lane >> 4) * 8;
        #pragma unroll 2
        for (int kt = 0; kt < 8; kt++) {
            const int granA = 2 * kt + (lane >> 4);
            const int granB = 2 * kt + ((lane >> 3) & 1);
            unsigned ah[4], al[4], bh[2][4];
            {
                const unsigned off = rowA * 256 + ((granA ^ (rowA & 7)) << 4);
                ldsm4(hiu + off, ah);
                ldsm4(lou + off, al);
            }
            #pragma unroll
            for (int p = 0; p < 2; p++) {
                const int row = 16 * p + rowB;
                const unsigned off = row * 256 + ((granB ^ (row & 7)) << 4);
                ldsm4(hiu + off, bh[p]);
            }
            #pragma unroll
            for (int nt = 0; nt < 4; nt++) {
                const unsigned* bfh = &bh[nt >> 1][(nt & 1) * 2];
                mma16816(c1[nt], ah, bfh);   // hi*hi
                mma16816(c1[nt], al, bfh);   // lo*hi
            }
        }
    }

    // ---------------- Softmax on C fragments (rows on lane>>2 groups) ------
    // c1[nt] = {(r,2q),(r,2q+1),(r+8,2q),(r+8,2q+1)}; cols 8nt+2q(+1).
    #pragma unroll
    for (int rh = 0; rh < 2; rh++) {
        float v[8];
        #pragma unroll
        for (int nt = 0; nt < 4; nt++) {
            v[2 * nt]     = c1[nt][2 * rh]     * SCALE;
            v[2 * nt + 1] = c1[nt][2 * rh + 1] * SCALE;
        }
        float m = v[0];
        #pragma unroll
        for (int j = 1; j < 8; j++) m = fmaxf(m, v[j]);
        m = fmaxf(m, __shfl_xor_sync(0xffffffffu, m, 1));
        m = fmaxf(m, __shfl_xor_sync(0xffffffffu, m, 2));
        float s = 0.0f;
        #pragma unroll
        for (int j = 0; j < 8; j++) { v[j] = __expf(v[j] - m); s += v[j]; }
        s += __shfl_xor_sync(0xffffffffu, s, 1);
        s += __shfl_xor_sync(0xffffffffu, s, 2);
        const float inv = 1.0f / s;
        #pragma unroll
        for (int nt = 0; nt < 4; nt++) {
            c1[nt][2 * rh]     = v[2 * nt]     * inv;
            c1[nt][2 * rh + 1] = v[2 * nt + 1] * inv;
        }
    }

    // ---------------- Repack attn C-frags -> GEMM2 A-frags (fp16) ----------
    unsigned a2[2][4];
    #pragma unroll
    for (int kt2 = 0; kt2 < 2; kt2++) {
        a2[kt2][0] = pk_h2(c1[2 * kt2][0],     c1[2 * kt2][1]);
        a2[kt2][1] = pk_h2(c1[2 * kt2][2],     c1[2 * kt2][3]);
        a2[kt2][2] = pk_h2(c1[2 * kt2 + 1][0], c1[2 * kt2 + 1][1]);
        a2[kt2][3] = pk_h2(c1[2 * kt2 + 1][2], c1[2 * kt2 + 1][3]);
    }

    // ---------------- GEMM2: out rows 16w.. = attn * hi  (k=32) ------------
    {
        float* outp = out + pos * (NHEADS * HD);
        const int q = lane & 3;
        const int r = lane >> 2;

        #pragma unroll
        for (int nc = 0; nc < 4; nc++) {            // 32-col output chunks
            float c2[4][4];
            #pragma unroll
            for (int dt = 0; dt < 4; dt++)
                #pragma unroll
                for (int z = 0; z < 4; z++) c2[dt][z] = 0.0f;

            #pragma unroll
            for (int kt2 = 0; kt2 < 2; kt2++) {
                const int rowG = 16 * kt2 + (lane & 7) + ((lane >> 3) & 1) * 8;
                unsigned b2h[2][4];
                #pragma unroll
                for (int p = 0; p < 2; p++) {
                    const int gran = 4 * nc + 2 * p + (lane >> 4);
                    const unsigned off = rowG * 256 + ((gran ^ (rowG & 7)) << 4);
                    ldsm4t(hiu + off, b2h[p]);
                }
                #pragma unroll
                for (int dt = 0; dt < 4; dt++)
                    mma16816(c2[dt], a2[kt2], &b2h[dt >> 1][(dt & 1) * 2]);
            }

            #pragma unroll
            for (int dt = 0; dt < 4; dt++) {
                const int col  = 32 * nc + 8 * dt + 2 * q;
                const int row0 = 16 * w + r;
                *reinterpret_cast<float2*>(&outp[row0 * HD + col])
                    = make_float2(c2[dt][0], c2[dt][1]);
                *reinterpret_cast<float2*>(&outp[(row0 + 8) * HD + col])
                    = make_float2(c2[dt][2], c2[dt][3]);
            }
        }
    }
}

extern "C" void kernel_launch(void* const* d_in, const int* in_sizes, int n_in,
                              void* d_out, int out_size) {
    const float* x        = (const float*)d_in[0];
    const float* patterns = (const float*)d_in[1];
    float* out            = (float*)d_out;
    const int positions   = in_sizes[0] / (NHEADS * HD);   // 16384
    fq_attn_kernel<<<positions, 64>>>(x, patterns, out);
}

// round 16
// speedup vs baseline: 2.8690x; 1.1268x over previous
#include <cuda_runtime.h>
#include <cuda_fp16.h>

// FastQuantumLLMOptimized: per-position cross-head attention, tensor-core path.
// x: [16384, 32, 128] f32, patterns: [32,128] f32.
//   xh = x_pos * patterns ; s = xh xh^T / sqrt(128); a = softmax(s); out = a xh
//
// TWO WARPS per position, ONE position per CTA (8.2KB smem, 10 CTAs = 20
// warps/SM). Warp w owns score/output rows 16w..16w+15.
// GEMMs via mma.sync.m16n8k16 (HMMA), xh quantized to fp16 once:
//   GEMM1: scores = hi*hi^T      (fp16 residual terms measured negligible
//                                 through softmax: +3e-6 rel_err per term)
//   GEMM2: out    = attn_fp16 * hi
// Softmax on fp32 C-fragments in registers; attn C-frags repack in-register
// to GEMM2 A-frags (fragment layouts coincide) — attn never touches smem.
//
// smem: xh fp16, 256B rows, 16B-granule XOR swizzle g^(h&7): every ldmatrix
// 8-lane address group covers 8 distinct bank-groups.

#define NHEADS 32
#define HD 128
#define SCALE 0.08838834764831845f   // 1/sqrt(128)

__device__ __forceinline__ unsigned smem_u32(const void* p) {
    unsigned r;
    asm("{ .reg .u64 t; cvta.to.shared.u64 t, %1; cvt.u32.u64 %0, t; }"
        : "=r"(r) : "l"(p));
    return r;
}
__device__ __forceinline__ void ldsm4(unsigned a, unsigned* r) {
    asm volatile("ldmatrix.sync.aligned.m8n8.x4.shared.b16 {%0,%1,%2,%3}, [%4];"
                 : "=r"(r[0]), "=r"(r[1]), "=r"(r[2]), "=r"(r[3]) : "r"(a));
}
__device__ __forceinline__ void ldsm4t(unsigned a, unsigned* r) {
    asm volatile("ldmatrix.sync.aligned.m8n8.x4.trans.shared.b16 {%0,%1,%2,%3}, [%4];"
                 : "=r"(r[0]), "=r"(r[1]), "=r"(r[2]), "=r"(r[3]) : "r"(a));
}
__device__ __forceinline__ void mma16816(float* c, const unsigned* a, const unsigned* b) {
    asm volatile("mma.sync.aligned.m16n8k16.row.col.f32.f16.f16.f32 "
                 "{%0,%1,%2,%3}, {%4,%5,%6,%7}, {%8,%9}, {%0,%1,%2,%3};"
                 : "+f"(c[0]), "+f"(c[1]), "+f"(c[2]), "+f"(c[3])
                 : "r"(a[0]), "r"(a[1]), "r"(a[2]), "r"(a[3]),
                   "r"(b[0]), "r"(b[1]));
}
// pack {lo, hi} fp32 -> f16x2 register (lo in lower half)
__device__ __forceinline__ unsigned pk_h2(float lo, float hi) {
    unsigned r;
    asm("cvt.rn.f16x2.f32 %0, %1, %2;" : "=r"(r) : "f"(hi), "f"(lo));
    return r;
}

__global__ __launch_bounds__(64, 10)
void fq_attn_kernel(const float* __restrict__ x,
                    const float* __restrict__ patterns,
                    float* __restrict__ out)
{
    __shared__ __align__(16) __half s_hi[NHEADS * HD];  // 8 KB

    const int lane = threadIdx.x & 31;
    const int w    = threadIdx.x >> 5;
    const long long pos = blockIdx.x;

    const unsigned hiu = smem_u32(s_hi);

    // ---------------- Phase 1: xh = x*patterns -> fp16 smem ----------------
    // warp w writes rows 16w..16w+15; lane owns 16B of each row.
    {
        const float4* x4 = reinterpret_cast<const float4*>(x + pos * (NHEADS * HD));
        const float4* p4 = reinterpret_cast<const float4*>(patterns);
        const int g   = lane >> 1;
        const int sub = (lane & 1) * 4;
        #pragma unroll 8
        for (int i = 0; i < 16; i++) {
            const int h = 16 * w + i;
            float4 xv = x4[h * 32 + lane];
            float4 pv = __ldg(&p4[h * 32 + lane]);
            float rx = xv.x * pv.x, ry = xv.y * pv.y;
            float rz = xv.z * pv.z, rw = xv.w * pv.w;
            const int idx = h * 128 + ((g ^ (h & 7)) << 3) + sub;
            uint2 hv;
            hv.x = pk_h2(rx, ry);
            hv.y = pk_h2(rz, rw);
            *reinterpret_cast<uint2*>(&s_hi[idx]) = hv;
        }
    }
    __syncthreads();

    // ---------------- GEMM1: S rows 16w.. = hi*hi^T ------------------------
    float c1[4][4];
    #pragma unroll
    for (int nt = 0; nt < 4; nt++)
        #pragma unroll
        for (int z = 0; z < 4; z++) c1[nt][z] = 0.0f;

    {
        const int rowA = 16 * w + (lane & 7) + ((lane >> 3) & 1) * 8;
        const int rowB = (lane & 7) + (lane >> 4) * 8;
        #pragma unroll 2
        for (int kt = 0; kt < 8; kt++) {
            const int granA = 2 * kt + (lane >> 4);
            const int granB = 2 * kt + ((lane >> 3) & 1);
            unsigned ah[4], bh[2][4];
            {
                const unsigned off = rowA * 256 + ((granA ^ (rowA & 7)) << 4);
                ldsm4(hiu + off, ah);
            }
            #pragma unroll
            for (int p = 0; p < 2; p++) {
                const int row = 16 * p + rowB;
                const unsigned off = row * 256 + ((granB ^ (row & 7)) << 4);
                ldsm4(hiu + off, bh[p]);
            }
            #pragma unroll
            for (int nt = 0; nt < 4; nt++)
                mma16816(c1[nt], ah, &bh[nt >> 1][(nt & 1) * 2]);
        }
    }

    // ---------------- Softmax on C fragments (rows on lane>>2 groups) ------
    // c1[nt] = {(r,2q),(r,2q+1),(r+8,2q),(r+8,2q+1)}; cols 8nt+2q(+1).
    #pragma unroll
    for (int rh = 0; rh < 2; rh++) {
        float v[8];
        #pragma unroll
        for (int nt = 0; nt < 4; nt++) {
            v[2 * nt]     = c1[nt][2 * rh]     * SCALE;
            v[2 * nt + 1] = c1[nt][2 * rh + 1] * SCALE;
        }
        float m = v[0];
        #pragma unroll
        for (int j = 1; j < 8; j++) m = fmaxf(m, v[j]);
        m = fmaxf(m, __shfl_xor_sync(0xffffffffu, m, 1));
        m = fmaxf(m, __shfl_xor_sync(0xffffffffu, m, 2));
        float s = 0.0f;
        #pragma unroll
        for (int j = 0; j < 8; j++) { v[j] = __expf(v[j] - m); s += v[j]; }
        s += __shfl_xor_sync(0xffffffffu, s, 1);
        s += __shfl_xor_sync(0xffffffffu, s, 2);
        const float inv = 1.0f / s;
        #pragma unroll
        for (int nt = 0; nt < 4; nt++) {
            c1[nt][2 * rh]     = v[2 * nt]     * inv;
            c1[nt][2 * rh + 1] = v[2 * nt + 1] * inv;
        }
    }

    // ---------------- Repack attn C-frags -> GEMM2 A-frags (fp16) ----------
    unsigned a2[2][4];
    #pragma unroll
    for (int kt2 = 0; kt2 < 2; kt2++) {
        a2[kt2][0] = pk_h2(c1[2 * kt2][0],     c1[2 * kt2][1]);
        a2[kt2][1] = pk_h2(c1[2 * kt2][2],     c1[2 * kt2][3]);
        a2[kt2][2] = pk_h2(c1[2 * kt2 + 1][0], c1[2 * kt2 + 1][1]);
        a2[kt2][3] = pk_h2(c1[2 * kt2 + 1][2], c1[2 * kt2 + 1][3]);
    }

    // ---------------- GEMM2: out rows 16w.. = attn * hi  (k=32) ------------
    {
        float* outp = out + pos * (NHEADS * HD);
        const int q = lane & 3;
        const int r = lane >> 2;

        #pragma unroll
        for (int nc = 0; nc < 4; nc++) {            // 32-col output chunks
            float c2[4][4];
            #pragma unroll
            for (int dt = 0; dt < 4; dt++)
                #pragma unroll
                for (int z = 0; z < 4; z++) c2[dt][z] = 0.0f;

            #pragma unroll
            for (int kt2 = 0; kt2 < 2; kt2++) {
                const int rowG = 16 * kt2 + (lane & 7) + ((lane >> 3) & 1) * 8;
                unsigned b2h[2][4];
                #pragma unroll
                for (int p = 0; p < 2; p++) {
                    const int gran = 4 * nc + 2 * p + (lane >> 4);
                    const unsigned off = rowG * 256 + ((gran ^ (rowG & 7)) << 4);
                    ldsm4t(hiu + off, b2h[p]);
                }
                #pragma unroll
                for (int dt = 0; dt < 4; dt++)
                    mma16816(c2[dt], a2[kt2], &b2h[dt >> 1][(dt & 1) * 2]);
            }

            #pragma unroll
            for (int dt = 0; dt < 4; dt++) {
                const int col  = 32 * nc + 8 * dt + 2 * q;
                const int row0 = 16 * w + r;
                *reinterpret_cast<float2*>(&outp[row0 * HD + col])
                    = make_float2(c2[dt][0], c2[dt][1]);
                *reinterpret_cast<float2*>(&outp[(row0 + 8) * HD + col])
                    = make_float2(c2[dt][2], c2[dt][3]);
            }
        }
    }
}

extern "C" void kernel_launch(void* const* d_in, const int* in_sizes, int n_in,
                              void* d_out, int out_size) {
    const float* x        = (const float*)d_in[0];
    const float* patterns = (const float*)d_in[1];
    float* out            = (float*)d_out;
    const int positions   = in_sizes[0] / (NHEADS * HD);   // 16384
    fq_attn_kernel<<<positions, 64>>>(x, patterns, out);
}